// round 14
// baseline (speedup 1.0000x reference)
#include <cuda_runtime.h>
#include <math.h>

#define BB 16
#define DD 512
#define HH 16
#define HD 32
#define LL 24
#define DFF 2048
#define NQKV 1536
#define TMAX 1024
#define NT 256
#define NCH 2  // attention T-chunks

// ---------------- device scratch ----------------
__device__ float g_h[BB * DD];
__device__ float g_h1[BB * DD];
__device__ float g_pqkv[4 * BB * NQKV];
__device__ float g_po[16 * BB * DD];
__device__ float g_pm1[4 * BB * DFF];
__device__ float g_p2[16 * BB * DD];
__device__ float g_am[BB * HH * NCH];
__device__ float g_as[BB * HH * NCH];
__device__ float g_ao[NCH * BB * HH * HD];
__device__ unsigned g_bar_count;
__device__ volatile unsigned g_bar_gen;

// ---------------- grid barrier ----------------
__device__ __forceinline__ void gsync() {
    __syncthreads();
    if (threadIdx.x == 0) {
        unsigned gen = g_bar_gen;
        __threadfence();
        if (atomicAdd(&g_bar_count, 1u) == gridDim.x - 1) {
            g_bar_count = 0;
            __threadfence();
            g_bar_gen = gen + 1;
        } else {
            while (g_bar_gen == gen) __nanosleep(64);
            __threadfence();
        }
    }
    __syncthreads();
}

// ---------------- prefetch helpers ----------------
__device__ __forceinline__ void pf_l1(const void* p) {
    asm volatile("prefetch.global.L1 [%0];" :: "l"(p));
}
__device__ __forceinline__ void pf_l2(const void* p) {
    asm volatile("prefetch.global.L2 [%0];" :: "l"(p));
}

// prefetch weight slice: rows [d0, d0+DS), cols [c0, c0+32) -> one line/row
template <int DS>
__device__ __forceinline__ void pf_w(const float* __restrict__ W, int N,
                                     int d0, int c0) {
    for (int d = threadIdx.x; d < DS; d += NT)
        pf_l1(W + (size_t)(d0 + d) * N + c0);
}

// prefetch K/V rows of this block's S2 attention chunk into L2
__device__ void pf_kv(const float* __restrict__ Kc, const float* __restrict__ Vc,
                      const int* __restrict__ kvlen, int bid) {
    if (bid >= 512) return;
    const int c = bid & 1, h = (bid >> 1) & 15, b = bid >> 5;
    const int T = kvlen[b];
    const int Ttot = T + 1;
    const int CH = (Ttot + NCH - 1) / NCH;
    const int t0 = c * CH;
    int t1 = t0 + CH; if (t1 > Ttot) t1 = Ttot;
    if (t1 > T) t1 = T;  // new-token row lives in smem, not cache
    const float* Kb = Kc + ((size_t)b * HH + h) * TMAX * HD;
    const float* Vb = Vc + ((size_t)b * HH + h) * TMAX * HD;
    for (int t = t0 + threadIdx.x; t < t1; t += NT) {
        pf_l2(Kb + (size_t)t * HD);
        pf_l2(Vb + (size_t)t * HD);
    }
}

// ---------------- plain preload: src[b][d0+d] -> xs[d][bb] ----------------
template <int DS>
__device__ __forceinline__ void preload_plain(const float* __restrict__ src, int ld,
                                              int d0, int b0, float* xs) {
    const int tid = threadIdx.x;
#pragma unroll
    for (int i = tid; i < DS * 8; i += NT) {
        int bb = i / DS, d = i % DS;
        xs[d * 12 + bb] = src[(size_t)(b0 + bb) * ld + d0 + d];
    }
    __syncthreads();
}

// ---------------- mlp2 preload: relu(b1 + sum of 4 mlp1 partials) --------
__device__ __forceinline__ void preload_relu(const float* __restrict__ b1,
                                             int d0, int b0, float* xs) {
    const int tid = threadIdx.x;
#pragma unroll
    for (int i = tid; i < 128 * 8; i += NT) {
        int bb = i >> 7, d = i & 127;
        int gd = d0 + d;
        float v = b1[gd];
#pragma unroll
        for (int s = 0; s < 4; s++)
            v += g_pm1[(size_t)(s * BB + b0 + bb) * DFF + gd];
        xs[d * 12 + bb] = fmaxf(v, 0.f);
    }
    __syncthreads();
}

// ---------------- outproj preload: merge NCH attention chunks ------------
__device__ __forceinline__ void preload_attn(int h, int b0, float* xs) {
    const int tid = threadIdx.x;
    const int bb = tid >> 5, j = tid & 31;
    const int b = b0 + bb;
    const int base = (b * HH + h) * NCH;
    float m0 = g_am[base + 0], m1 = g_am[base + 1];
    float m = fmaxf(m0, m1);
    float w0 = __expf(m0 - m), w1 = __expf(m1 - m);
    float S = g_as[base + 0] * w0 + g_as[base + 1] * w1;
    const size_t ob = ((size_t)b * HH + h) * HD + j;
    float o = g_ao[ob] * w0 + g_ao[(size_t)BB * HH * HD + ob] * w1;
    xs[j * 12 + bb] = o / S;
    __syncthreads();
}

// ---------------- gemv core: 32 cols x 8 batches over DS K-dims ----------
template <int DS>
__device__ __forceinline__ void gemv_core(const float* __restrict__ W, int N,
                                          int d0, int c0,
                                          float* __restrict__ out, int ldo,
                                          int b0, float* xs, float* red) {
    const int tid = threadIdx.x, lane = tid & 31, w = tid >> 5;
    constexpr int DW = DS / 8;
    const float* Wp = W + (size_t)(d0 + w * DW) * N + c0 + lane;
    const float* xp = xs + (size_t)(w * DW) * 12;
    float a0 = 0, a1 = 0, a2 = 0, a3 = 0, a4 = 0, a5 = 0, a6 = 0, a7 = 0;
#pragma unroll
    for (int d = 0; d < DW; d++) {
        float wv = Wp[(size_t)d * N];
        float4 xa = *(const float4*)(xp + d * 12);
        float4 xb = *(const float4*)(xp + d * 12 + 4);
        a0 += xa.x * wv; a1 += xa.y * wv; a2 += xa.z * wv; a3 += xa.w * wv;
        a4 += xb.x * wv; a5 += xb.y * wv; a6 += xb.z * wv; a7 += xb.w * wv;
    }
    float* rp = red + (size_t)tid * 9;
    rp[0] = a0; rp[1] = a1; rp[2] = a2; rp[3] = a3;
    rp[4] = a4; rp[5] = a5; rp[6] = a6; rp[7] = a7;
    __syncthreads();
    const int cc = tid & 31, bb = tid >> 5;
    float v = 0.f;
#pragma unroll
    for (int w2 = 0; w2 < 8; w2++) v += red[(size_t)(w2 * 32 + cc) * 9 + bb];
    out[(size_t)(b0 + bb) * ldo + c0 + cc] = v;
    __syncthreads();
}

// ---------------- attention chunk: one (b, h, c) ----------------
__device__ void attn_chunk(const float* __restrict__ Kc, const float* __restrict__ Vc,
                           const float* __restrict__ bq,
                           const int* __restrict__ kvlen,
                           int b, int h, int c, float* sm) {
    float* sc   = sm;         // [392]
    float* qs   = sm + 392;   // [32]
    float* kns  = sm + 424;   // [32]
    float* vns  = sm + 456;   // [32]
    float* redv = sm + 488;   // [8][32]
    float* rr   = sm + 744;   // [8]
    float* fin  = sm + 752;   // [2]

    const int tid = threadIdx.x, wid = tid >> 5, lane = tid & 31;
    const int T = kvlen[b];
    const int Ttot = T + 1;
    const int CH = (Ttot + NCH - 1) / NCH;
    const int t0 = c * CH;
    const int t1 = (t0 + CH < Ttot) ? (t0 + CH) : Ttot;
    const float scale = 0.17677669529663687f;

    // merge qkv partials (4 slices) for q / k_new / v_new
    if (tid < 96) {
        int which = tid >> 5, j = tid & 31;
        int col = which * DD + h * HD + j;
        float v = bq[col];
#pragma unroll
        for (int s = 0; s < 4; s++) v += g_pqkv[(size_t)(s * BB + b) * NQKV + col];
        if (which == 0) qs[j] = v;
        else if (which == 1) kns[j] = v;
        else vns[j] = v;
    }
    __syncthreads();

    const int outi = (b * HH + h) * NCH + c;
    const size_t ob = ((size_t)b * HH + h) * HD;

    if (t1 <= t0) {
        if (tid == 0) { g_am[outi] = -1e30f; g_as[outi] = 0.f; }
        if (tid < HD) g_ao[(size_t)(c * BB) * HH * HD + ob + tid] = 0.f;
        return;
    }

    const float* Kb = Kc + ((size_t)b * HH + h) * TMAX * HD;
    const float* Vb = Vc + ((size_t)b * HH + h) * TMAX * HD;
    const int len = t1 - t0;

    // score pass: thread per timestep
    for (int t = t0 + tid; t < t1; t += NT) {
        const float* kp = (t < T) ? (Kb + (size_t)t * HD) : kns;
        float s = 0.f;
#pragma unroll
        for (int i = 0; i < 8; i++) {
            float4 k4 = *(const float4*)(kp + i * 4);
            float4 q4 = *(const float4*)(qs + i * 4);
            s += k4.x * q4.x + k4.y * q4.y + k4.z * q4.z + k4.w * q4.w;
        }
        sc[t - t0] = s * scale;
    }
    __syncthreads();

    // chunk max
    float m = -1e30f;
    for (int i = tid; i < len; i += NT) m = fmaxf(m, sc[i]);
#pragma unroll
    for (int o = 16; o; o >>= 1) m = fmaxf(m, __shfl_xor_sync(0xffffffffu, m, o));
    if (lane == 0) rr[wid] = m;
    __syncthreads();
    if (tid == 0) {
        float mm = rr[0];
#pragma unroll
        for (int w = 1; w < 8; w++) mm = fmaxf(mm, rr[w]);
        fin[0] = mm;
    }
    __syncthreads();
    m = fin[0];

    // exp + sum
    float s = 0.f;
    for (int i = tid; i < len; i += NT) {
        float e = __expf(sc[i] - m);
        sc[i] = e;
        s += e;
    }
#pragma unroll
    for (int o = 16; o; o >>= 1) s += __shfl_xor_sync(0xffffffffu, s, o);
    if (lane == 0) rr[wid] = s;
    __syncthreads();
    if (tid == 0) {
        float ss = rr[0];
#pragma unroll
        for (int w = 1; w < 8; w++) ss += rr[w];
        g_am[outi] = m;
        g_as[outi] = ss;
    }

    // V pass: warp covers 4 timesteps/iter; 4 independent acc chains
    const int tq = lane >> 3, dq = lane & 7;
    float4 a0 = make_float4(0.f, 0.f, 0.f, 0.f);
    float4 a1 = a0, a2 = a0, a3 = a0;
    const int tb = t0 + wid * 4 + tq;
    for (int t = tb; t < t1; t += 128) {
        {
            float wgt = sc[t - t0];
            const float* vp = (t < T) ? (Vb + (size_t)t * HD) : vns;
            float4 v4 = *(const float4*)(vp + dq * 4);
            a0.x += wgt * v4.x; a0.y += wgt * v4.y;
            a0.z += wgt * v4.z; a0.w += wgt * v4.w;
        }
        if (t + 32 < t1) {
            float wgt = sc[t + 32 - t0];
            const float* vp = (t + 32 < T) ? (Vb + (size_t)(t + 32) * HD) : vns;
            float4 v4 = *(const float4*)(vp + dq * 4);
            a1.x += wgt * v4.x; a1.y += wgt * v4.y;
            a1.z += wgt * v4.z; a1.w += wgt * v4.w;
        }
        if (t + 64 < t1) {
            float wgt = sc[t + 64 - t0];
            const float* vp = (t + 64 < T) ? (Vb + (size_t)(t + 64) * HD) : vns;
            float4 v4 = *(const float4*)(vp + dq * 4);
            a2.x += wgt * v4.x; a2.y += wgt * v4.y;
            a2.z += wgt * v4.z; a2.w += wgt * v4.w;
        }
        if (t + 96 < t1) {
            float wgt = sc[t + 96 - t0];
            const float* vp = (t + 96 < T) ? (Vb + (size_t)(t + 96) * HD) : vns;
            float4 v4 = *(const float4*)(vp + dq * 4);
            a3.x += wgt * v4.x; a3.y += wgt * v4.y;
            a3.z += wgt * v4.z; a3.w += wgt * v4.w;
        }
    }
    float4 acc;
    acc.x = (a0.x + a1.x) + (a2.x + a3.x);
    acc.y = (a0.y + a1.y) + (a2.y + a3.y);
    acc.z = (a0.z + a1.z) + (a2.z + a3.z);
    acc.w = (a0.w + a1.w) + (a2.w + a3.w);
#pragma unroll
    for (int o = 8; o <= 16; o <<= 1) {
        acc.x += __shfl_xor_sync(0xffffffffu, acc.x, o);
        acc.y += __shfl_xor_sync(0xffffffffu, acc.y, o);
        acc.z += __shfl_xor_sync(0xffffffffu, acc.z, o);
        acc.w += __shfl_xor_sync(0xffffffffu, acc.w, o);
    }
    if (tq == 0) *(float4*)(redv + wid * 32 + dq * 4) = acc;
    __syncthreads();
    if (tid < HD) {
        float o = 0.f;
#pragma unroll
        for (int w = 0; w < 8; w++) o += redv[w * 32 + tid];
        g_ao[(size_t)(c * BB) * HH * HD + ob + tid] = o;
    }
}

// ---------------- LN stage: one batch, merge S partials + resid + bias ---
template <int S>
__device__ void ln_stage(const float* __restrict__ part,
                         const float* __restrict__ resid,
                         const float* __restrict__ bias,
                         const float* __restrict__ gam,
                         const float* __restrict__ bet,
                         float* __restrict__ out, int b, float* sm) {
    const int tid = threadIdx.x, lane = tid & 31, wid = tid >> 5;
    float v0, v1;
    {
        int j = tid;
        float t = resid[(size_t)b * DD + j] + bias[j];
#pragma unroll
        for (int s = 0; s < S; s++) t += part[(size_t)(s * BB + b) * DD + j];
        v0 = t;
        j = tid + 256;
        t = resid[(size_t)b * DD + j] + bias[j];
#pragma unroll
        for (int s = 0; s < S; s++) t += part[(size_t)(s * BB + b) * DD + j];
        v1 = t;
    }
    float s1 = v0 + v1, s2 = v0 * v0 + v1 * v1;
#pragma unroll
    for (int o = 16; o; o >>= 1) {
        s1 += __shfl_xor_sync(0xffffffffu, s1, o);
        s2 += __shfl_xor_sync(0xffffffffu, s2, o);
    }
    float* rs = sm; float* rq = sm + 8; float* mv = sm + 16;
    if (lane == 0) { rs[wid] = s1; rq[wid] = s2; }
    __syncthreads();
    if (tid == 0) {
        float a = 0.f, q = 0.f;
#pragma unroll
        for (int w = 0; w < 8; w++) { a += rs[w]; q += rq[w]; }
        float mean = a / DD;
        mv[0] = mean;
        mv[1] = rsqrtf(q / DD - mean * mean + 1e-5f);
    }
    __syncthreads();
    const float mean = mv[0], rstd = mv[1];
    out[(size_t)b * DD + tid] = (v0 - mean) * rstd * gam[tid] + bet[tid];
    out[(size_t)b * DD + tid + 256] =
        (v1 - mean) * rstd * gam[tid + 256] + bet[tid + 256];
    __syncthreads();
}

// ---------------- persistent kernel ----------------
__global__ void __launch_bounds__(NT, 4)
decoder_kernel(const float* __restrict__ x,
               const float* __restrict__ kc, const float* __restrict__ vc,
               const float* __restrict__ ln1g, const float* __restrict__ ln1b,
               const float* __restrict__ qkvw, const float* __restrict__ qkvb,
               const float* __restrict__ outw, const float* __restrict__ outb,
               const float* __restrict__ ln2g, const float* __restrict__ ln2b,
               const float* __restrict__ w1, const float* __restrict__ b1,
               const float* __restrict__ w2, const float* __restrict__ b2,
               const int* __restrict__ kvlen, float* __restrict__ dout) {
    extern __shared__ float sm[];
    float* xs  = sm;             // [128][12] max
    float* red = sm + 128 * 12;  // [256][9]
    const int bid = blockIdx.x;

    for (int l = 0; l < LL; l++) {
        const float* Wq = qkvw + (size_t)l * DD * NQKV;
        const float* bq = qkvb + (size_t)l * NQKV;
        const float* Wo = outw + (size_t)l * DD * DD;
        const float* bo = outb + (size_t)l * DD;
        const float* W1 = w1 + (size_t)l * DD * DFF;
        const float* B1 = b1 + (size_t)l * DFF;
        const float* W2 = w2 + (size_t)l * DFF * DD;
        const float* Kc = kc + (size_t)l * BB * HH * TMAX * HD;
        const float* Vc = vc + (size_t)l * BB * HH * TMAX * HD;

        // S0: produce g_h (x for l==0, else LN2 of prev layer). 16 vblocks.
        if (l == 0) {
            for (int i = bid * NT + threadIdx.x; i < BB * DD;
                 i += gridDim.x * NT)
                g_h[i] = x[i];
            // layer-0: also prefetch this block's S2 KV chunk early
            pf_kv(Kc, Vc, kvlen, bid);
        } else {
            for (int vb = bid; vb < 16; vb += gridDim.x)
                ln_stage<16>(g_p2, g_h1, b2 + (size_t)(l - 1) * DD,
                             ln2g + (size_t)(l - 1) * DD,
                             ln2b + (size_t)(l - 1) * DD, g_h, vb, sm);
        }
        // prefetch S1 weight slice to L1 (592 blocks idle here anyway)
        if (bid < 384) {
            int ks = bid & 3, c0 = (bid >> 3) * 32;
            pf_w<128>(Wq, NQKV, ks * 128, c0);
        }
        gsync();

        // S1: qkv split-K4 (DS=128). 384 vblocks (1 round on 608).
        for (int vb = bid; vb < 384; vb += gridDim.x) {
            int ks = vb & 3, b0 = ((vb >> 2) & 1) * 8, c0 = (vb >> 3) * 32;
            preload_plain<128>(g_h, DD, ks * 128, b0, xs);
            gemv_core<128>(Wq, NQKV, ks * 128, c0,
                           g_pqkv + (size_t)ks * BB * NQKV, NQKV, b0, xs, red);
        }
        // re-touch S2 KV chunk (L2) before the attention stage
        pf_kv(Kc, Vc, kvlen, bid);
        gsync();

        // S2: attention T-split 2. 512 vblocks (1 round).
        for (int vb = bid; vb < 512; vb += gridDim.x) {
            int c = vb & 1, h = (vb >> 1) & 15, b = vb >> 5;
            attn_chunk(Kc, Vc, bq, kvlen, b, h, c, sm);
        }
        // prefetch S3 weight slice to L1
        if (bid < 512) {
            int ks = bid & 15, c0 = (bid >> 5) * 32;
            pf_w<32>(Wo, DD, ks * 32, c0);
        }
        gsync();

        // S3: outproj split-K16 (DS=32), attn merge in preload. 512 vblocks.
        for (int vb = bid; vb < 512; vb += gridDim.x) {
            int ks = vb & 15, b0 = ((vb >> 4) & 1) * 8, c0 = (vb >> 5) * 32;
            preload_attn(ks, b0, xs);  // h == ks since DS == HD
            gemv_core<32>(Wo, DD, ks * 32, c0,
                          g_po + (size_t)ks * BB * DD, DD, b0, xs, red);
        }
        gsync();

        // S4: LN1 (merge 16 outproj partials + residual g_h + bo). 16 vblocks.
        for (int vb = bid; vb < 16; vb += gridDim.x)
            ln_stage<16>(g_po, g_h, bo, ln1g + (size_t)l * DD,
                         ln1b + (size_t)l * DD, g_h1, vb, sm);
        // prefetch S5 weight slice to L1 (592 blocks idle here anyway)
        if (bid < 512) {
            int ks = bid & 3, c0 = (bid >> 3) * 32;
            pf_w<128>(W1, DFF, ks * 128, c0);
        }
        gsync();

        // S5: mlp1 split-K4 (DS=128). 512 vblocks.
        for (int vb = bid; vb < 512; vb += gridDim.x) {
            int ks = vb & 3, b0 = ((vb >> 2) & 1) * 8, c0 = (vb >> 3) * 32;
            preload_plain<128>(g_h1, DD, ks * 128, b0, xs);
            gemv_core<128>(W1, DFF, ks * 128, c0,
                           g_pm1 + (size_t)ks * BB * DFF, DFF, b0, xs, red);
        }
        // prefetch S6 weight slice to L1
        if (bid < 512) {
            int ks = bid & 15, c0 = (bid >> 5) * 32;
            pf_w<128>(W2, DD, ks * 128, c0);
        }
        gsync();

        // S6: mlp2 split-K16 (DS=128), relu+merge in preload. 512 vblocks.
        for (int vb = bid; vb < 512; vb += gridDim.x) {
            int ks = vb & 15, b0 = ((vb >> 4) & 1) * 8, c0 = (vb >> 5) * 32;
            preload_relu(B1, ks * 128, b0, xs);
            gemv_core<128>(W2, DD, ks * 128, c0,
                           g_p2 + (size_t)ks * BB * DD, DD, b0, xs, red);
        }
        // prefetch NEXT layer's S2 KV chunk into L2 (overlaps S0/S1)
        if (l + 1 < LL)
            pf_kv(kc + (size_t)(l + 1) * BB * HH * TMAX * HD,
                  vc + (size_t)(l + 1) * BB * HH * TMAX * HD, kvlen, bid);
        gsync();
    }

    // final: LN2 of last layer -> d_out. 16 vblocks.
    for (int vb = bid; vb < 16; vb += gridDim.x)
        ln_stage<16>(g_p2, g_h1, b2 + (size_t)(LL - 1) * DD,
                     ln2g + (size_t)(LL - 1) * DD,
                     ln2b + (size_t)(LL - 1) * DD, dout, vb, sm);
}

// ---------------- launcher ----------------
extern "C" void kernel_launch(void* const* d_in, const int* in_sizes, int n_in,
                              void* d_out, int out_size) {
    (void)in_sizes; (void)n_in; (void)out_size;
    const float* x    = (const float*)d_in[0];
    const float* kc   = (const float*)d_in[1];
    const float* vc   = (const float*)d_in[2];
    const float* ln1g = (const float*)d_in[3];
    const float* ln1b = (const float*)d_in[4];
    const float* qkvw = (const float*)d_in[5];
    const float* qkvb = (const float*)d_in[6];
    const float* outw = (const float*)d_in[7];
    const float* outb = (const float*)d_in[8];
    const float* ln2g = (const float*)d_in[9];
    const float* ln2b = (const float*)d_in[10];
    const float* w1   = (const float*)d_in[11];
    const float* b1   = (const float*)d_in[12];
    const float* w2   = (const float*)d_in[13];
    const float* b2   = (const float*)d_in[14];
    const int* kvlen  = (const int*)d_in[16];

    static int grid = 0;
    const int SMEM = (128 * 12 + 256 * 9) * 4;  // 15360 bytes
    if (!grid) {
        cudaFuncSetAttribute(decoder_kernel,
                             cudaFuncAttributeMaxDynamicSharedMemorySize, SMEM);
        int dev = 0;
        cudaGetDevice(&dev);
        cudaDeviceProp prop;
        cudaGetDeviceProperties(&prop, dev);
        int occ = 0;
        cudaOccupancyMaxActiveBlocksPerMultiprocessor(&occ, decoder_kernel,
                                                      NT, SMEM);
        if (occ < 1) occ = 1;
        if (occ > 4) occ = 4;
        grid = prop.multiProcessorCount * occ;
    }

    decoder_kernel<<<grid, NT, SMEM>>>(
        x, kc, vc, ln1g, ln1b, qkvw, qkvb, outw, outb, ln2g, ln2b,
        w1, b1, w2, b2, kvlen, (float*)d_out);
}

// round 15
// speedup vs baseline: 1.3495x; 1.3495x over previous
#include <cuda_runtime.h>
#include <math.h>

#define BB 16
#define DD 512
#define HH 16
#define HD 32
#define LL 24
#define DFF 2048
#define NQKV 1536
#define TMAX 1024
#define NT 256
#define NCH 2  // attention T-chunks

// attention smem tile geometry
#define TROWS 64
#define RSTRIDE 36            // floats per row (padded)
#define TILEF (TROWS * RSTRIDE)  // 2304 floats per buffer
#define KOFF 368
#define VOFF (368 + 2 * TILEF)
#define ATTN_SMEM (368 + 4 * TILEF)   // 9584 floats

// ---------------- device scratch ----------------
__device__ float g_h[BB * DD];
__device__ float g_h1[BB * DD];
__device__ float g_pqkv[4 * BB * NQKV];
__device__ float g_po[16 * BB * DD];
__device__ float g_pm1[4 * BB * DFF];
__device__ float g_p2[16 * BB * DD];
__device__ float g_as[BB * HH * NCH];      // per-chunk exp-sum (no-max)
__device__ float g_ao[NCH * BB * HH * HD]; // per-chunk unnormalized V-acc
__device__ unsigned g_bar_count;
__device__ volatile unsigned g_bar_gen;

// ---------------- grid barrier ----------------
__device__ __forceinline__ void gsync() {
    __syncthreads();
    if (threadIdx.x == 0) {
        unsigned gen = g_bar_gen;
        __threadfence();
        if (atomicAdd(&g_bar_count, 1u) == gridDim.x - 1) {
            g_bar_count = 0;
            __threadfence();
            g_bar_gen = gen + 1;
        } else {
            while (g_bar_gen == gen) __nanosleep(64);
            __threadfence();
        }
    }
    __syncthreads();
}

// ---------------- cp.async helpers ----------------
__device__ __forceinline__ void cpa16(unsigned dst, const void* src) {
    asm volatile("cp.async.cg.shared.global [%0], [%1], 16;"
                 :: "r"(dst), "l"(src));
}

// ---------------- plain preload: src[b][d0+d] -> xs[d][bb] ----------------
template <int DS>
__device__ __forceinline__ void preload_plain(const float* __restrict__ src, int ld,
                                              int d0, int b0, float* xs) {
    const int tid = threadIdx.x;
#pragma unroll
    for (int i = tid; i < DS * 8; i += NT) {
        int bb = i / DS, d = i % DS;
        xs[d * 12 + bb] = src[(size_t)(b0 + bb) * ld + d0 + d];
    }
    __syncthreads();
}

// ---------------- mlp2 preload: relu(b1 + sum of 4 mlp1 partials) --------
__device__ __forceinline__ void preload_relu(const float* __restrict__ b1,
                                             int d0, int b0, float* xs) {
    const int tid = threadIdx.x;
#pragma unroll
    for (int i = tid; i < 128 * 8; i += NT) {
        int bb = i >> 7, d = i & 127;
        int gd = d0 + d;
        float v = b1[gd];
#pragma unroll
        for (int s = 0; s < 4; s++)
            v += g_pm1[(size_t)(s * BB + b0 + bb) * DFF + gd];
        xs[d * 12 + bb] = fmaxf(v, 0.f);
    }
    __syncthreads();
}

// ---------------- outproj preload: sum-merge NCH attention chunks --------
__device__ __forceinline__ void preload_attn(int h, int b0, float* xs) {
    const int tid = threadIdx.x;
    const int bb = tid >> 5, j = tid & 31;
    const int b = b0 + bb;
    const int base = (b * HH + h) * NCH;
    float S = g_as[base + 0] + g_as[base + 1];
    const size_t ob = ((size_t)b * HH + h) * HD + j;
    float o = g_ao[ob] + g_ao[(size_t)BB * HH * HD + ob];
    xs[j * 12 + bb] = o / S;
    __syncthreads();
}

// ---------------- gemv core: 32 cols x 8 batches over DS K-dims ----------
template <int DS>
__device__ __forceinline__ void gemv_core(const float* __restrict__ W, int N,
                                          int d0, int c0,
                                          float* __restrict__ out, int ldo,
                                          int b0, float* xs, float* red) {
    const int tid = threadIdx.x, lane = tid & 31, w = tid >> 5;
    constexpr int DW = DS / 8;
    const float* Wp = W + (size_t)(d0 + w * DW) * N + c0 + lane;
    const float* xp = xs + (size_t)(w * DW) * 12;
    float a0 = 0, a1 = 0, a2 = 0, a3 = 0, a4 = 0, a5 = 0, a6 = 0, a7 = 0;
#pragma unroll
    for (int d = 0; d < DW; d++) {
        float wv = Wp[(size_t)d * N];
        float4 xa = *(const float4*)(xp + d * 12);
        float4 xb = *(const float4*)(xp + d * 12 + 4);
        a0 += xa.x * wv; a1 += xa.y * wv; a2 += xa.z * wv; a3 += xa.w * wv;
        a4 += xb.x * wv; a5 += xb.y * wv; a6 += xb.z * wv; a7 += xb.w * wv;
    }
    float* rp = red + (size_t)tid * 9;
    rp[0] = a0; rp[1] = a1; rp[2] = a2; rp[3] = a3;
    rp[4] = a4; rp[5] = a5; rp[6] = a6; rp[7] = a7;
    __syncthreads();
    const int cc = tid & 31, bb = tid >> 5;
    float v = 0.f;
#pragma unroll
    for (int w2 = 0; w2 < 8; w2++) v += red[(size_t)(w2 * 32 + cc) * 9 + bb];
    out[(size_t)(b0 + bb) * ldo + c0 + cc] = v;
    __syncthreads();
}

// ---------------- attention tile stager (cp.async) ----------------
__device__ __forceinline__ void attn_stage(const float* __restrict__ Kb,
                                           const float* __restrict__ Vb,
                                           int tb, int kv_end, int buf,
                                           unsigned smbase) {
    const int tid = threadIdx.x;
#pragma unroll
    for (int k = 0; k < 4; k++) {
        int seg = tid + k * 256;       // 0..1023
        int isV = seg >> 9;
        int s2 = seg & 511;
        int row = s2 >> 3, dq = s2 & 7;
        int trow = tb + row;
        if (trow < kv_end) {
            const float* src = (isV ? Vb : Kb) + (size_t)trow * HD + dq * 4;
            unsigned dst = smbase +
                ((isV ? VOFF : KOFF) + buf * TILEF + row * RSTRIDE + dq * 4) * 4;
            cpa16(dst, src);
        }
    }
    asm volatile("cp.async.commit_group;");
}

// ---------------- attention chunk: one (b, h, c) --------------------------
// single-pass no-max softmax; cp.async double-buffered KV tiles in smem.
__device__ void attn_chunk(const float* __restrict__ Kc, const float* __restrict__ Vc,
                           const float* __restrict__ bq,
                           const int* __restrict__ kvlen,
                           int b, int h, int c, float* sm, unsigned smbase) {
    float* qkv96 = sm;        // [96]: q | k_new | v_new
    float* redv  = sm + 96;   // [8][32]
    float* rsum  = sm + 352;  // [8]

    const int tid = threadIdx.x, wid = tid >> 5, lane = tid & 31;
    const int T = kvlen[b];
    const int Ttot = T + 1;
    const int CH = (Ttot + NCH - 1) / NCH;
    const int t0 = c * CH;
    int t1 = t0 + CH; if (t1 > Ttot) t1 = Ttot;
    const float scale = 0.17677669529663687f;

    // merge qkv partials (4 slices) for q / k_new / v_new
    if (tid < 96) {
        int which = tid >> 5, j = tid & 31;
        int col = which * DD + h * HD + j;
        float v = bq[col];
#pragma unroll
        for (int s = 0; s < 4; s++)
            v += g_pqkv[(size_t)(s * BB + b) * NQKV + col];
        qkv96[which * 32 + j] = v;
    }
    __syncthreads();

    const int outi = (b * HH + h) * NCH + c;
    const size_t ob = ((size_t)b * HH + h) * HD;

    if (t0 >= t1) {
        if (tid == 0) g_as[outi] = 0.f;
        if (tid < HD) g_ao[(size_t)c * BB * HH * HD + ob + tid] = 0.f;
        __syncthreads();
        return;
    }

    const float* Kb = Kc + ((size_t)b * HH + h) * TMAX * HD;
    const float* Vb = Vc + ((size_t)b * HH + h) * TMAX * HD;
    const int kv_end = (t1 < T) ? t1 : T;  // cached rows only
    const int len = kv_end - t0;
    const int ntiles = (len + TROWS - 1) / TROWS;

    const int tq = lane >> 3, dq = lane & 7;
    const float4 q4 = *(const float4*)(qkv96 + dq * 4);
    float4 acc = make_float4(0.f, 0.f, 0.f, 0.f);
    float ssum = 0.f;

    if (ntiles > 0) attn_stage(Kb, Vb, t0, kv_end, 0, smbase);
    for (int i = 0; i < ntiles; i++) {
        if (i + 1 < ntiles) {
            attn_stage(Kb, Vb, t0 + (i + 1) * TROWS, kv_end, (i + 1) & 1, smbase);
            asm volatile("cp.async.wait_group 1;");
        } else {
            asm volatile("cp.async.wait_group 0;");
        }
        __syncthreads();
        const float* Kt = sm + KOFF + (i & 1) * TILEF;
        const float* Vt = sm + VOFF + (i & 1) * TILEF;
        const int tb = t0 + i * TROWS;
#pragma unroll
        for (int j = 0; j < 2; j++) {
            int row = wid * 8 + j * 4 + tq;
            bool valid = (tb + row) < kv_end;
            float4 k4 = *(const float4*)(Kt + row * RSTRIDE + dq * 4);
            float s = k4.x * q4.x + k4.y * q4.y + k4.z * q4.z + k4.w * q4.w;
            s += __shfl_xor_sync(0xffffffffu, s, 1);
            s += __shfl_xor_sync(0xffffffffu, s, 2);
            s += __shfl_xor_sync(0xffffffffu, s, 4);
            float e = valid ? __expf(s * scale) : 0.f;
            float4 v4 = *(const float4*)(Vt + row * RSTRIDE + dq * 4);
            ssum += e;
            acc.x += e * v4.x; acc.y += e * v4.y;
            acc.z += e * v4.z; acc.w += e * v4.w;
        }
        __syncthreads();
    }

    // new token at position T (only in the chunk containing Ttot-1)
    if (t1 > T && wid == 0) {
        const float* kns = qkv96 + 32;
        const float* vns = qkv96 + 64;
        float4 k4 = *(const float4*)(kns + dq * 4);
        float s = k4.x * q4.x + k4.y * q4.y + k4.z * q4.z + k4.w * q4.w;
        s += __shfl_xor_sync(0xffffffffu, s, 1);
        s += __shfl_xor_sync(0xffffffffu, s, 2);
        s += __shfl_xor_sync(0xffffffffu, s, 4);
        float e = (tq == 0) ? __expf(s * scale) : 0.f;
        float4 v4 = *(const float4*)(vns + dq * 4);
        ssum += e;
        acc.x += e * v4.x; acc.y += e * v4.y;
        acc.z += e * v4.z; acc.w += e * v4.w;
    }

    // reduce: acc over tq groups; ssum over full warp (8 dq lanes overcount)
#pragma unroll
    for (int o = 8; o <= 16; o <<= 1) {
        acc.x += __shfl_xor_sync(0xffffffffu, acc.x, o);
        acc.y += __shfl_xor_sync(0xffffffffu, acc.y, o);
        acc.z += __shfl_xor_sync(0xffffffffu, acc.z, o);
        acc.w += __shfl_xor_sync(0xffffffffu, acc.w, o);
    }
#pragma unroll
    for (int o = 16; o; o >>= 1) ssum += __shfl_xor_sync(0xffffffffu, ssum, o);
    if (tq == 0) *(float4*)(redv + wid * 32 + dq * 4) = acc;
    if (lane == 0) rsum[wid] = ssum;
    __syncthreads();
    if (tid < HD) {
        float o = 0.f;
#pragma unroll
        for (int w = 0; w < 8; w++) o += redv[w * 32 + tid];
        g_ao[(size_t)c * BB * HH * HD + ob + tid] = o;
    }
    if (tid == 0) {
        float ss = 0.f;
#pragma unroll
        for (int w = 0; w < 8; w++) ss += rsum[w];
        g_as[outi] = ss * 0.125f;
    }
    __syncthreads();
}

// ---------------- LN stage: one batch, merge S partials + resid + bias ---
template <int S>
__device__ void ln_stage(const float* __restrict__ part,
                         const float* __restrict__ resid,
                         const float* __restrict__ bias,
                         const float* __restrict__ gam,
                         const float* __restrict__ bet,
                         float* __restrict__ out, int b, float* sm) {
    const int tid = threadIdx.x, lane = tid & 31, wid = tid >> 5;
    float v0, v1;
    {
        int j = tid;
        float t = resid[(size_t)b * DD + j] + bias[j];
#pragma unroll
        for (int s = 0; s < S; s++) t += part[(size_t)(s * BB + b) * DD + j];
        v0 = t;
        j = tid + 256;
        t = resid[(size_t)b * DD + j] + bias[j];
#pragma unroll
        for (int s = 0; s < S; s++) t += part[(size_t)(s * BB + b) * DD + j];
        v1 = t;
    }
    float s1 = v0 + v1, s2 = v0 * v0 + v1 * v1;
#pragma unroll
    for (int o = 16; o; o >>= 1) {
        s1 += __shfl_xor_sync(0xffffffffu, s1, o);
        s2 += __shfl_xor_sync(0xffffffffu, s2, o);
    }
    float* rs = sm; float* rq = sm + 8; float* mv = sm + 16;
    if (lane == 0) { rs[wid] = s1; rq[wid] = s2; }
    __syncthreads();
    if (tid == 0) {
        float a = 0.f, q = 0.f;
#pragma unroll
        for (int w = 0; w < 8; w++) { a += rs[w]; q += rq[w]; }
        float mean = a / DD;
        mv[0] = mean;
        mv[1] = rsqrtf(q / DD - mean * mean + 1e-5f);
    }
    __syncthreads();
    const float mean = mv[0], rstd = mv[1];
    out[(size_t)b * DD + tid] = (v0 - mean) * rstd * gam[tid] + bet[tid];
    out[(size_t)b * DD + tid + 256] =
        (v1 - mean) * rstd * gam[tid + 256] + bet[tid + 256];
    __syncthreads();
}

// ---------------- persistent kernel ----------------
__global__ void __launch_bounds__(NT, 4)
decoder_kernel(const float* __restrict__ x,
               const float* __restrict__ kc, const float* __restrict__ vc,
               const float* __restrict__ ln1g, const float* __restrict__ ln1b,
               const float* __restrict__ qkvw, const float* __restrict__ qkvb,
               const float* __restrict__ outw, const float* __restrict__ outb,
               const float* __restrict__ ln2g, const float* __restrict__ ln2b,
               const float* __restrict__ w1, const float* __restrict__ b1,
               const float* __restrict__ w2, const float* __restrict__ b2,
               const int* __restrict__ kvlen, float* __restrict__ dout) {
    extern __shared__ float sm[];
    float* xs  = sm;             // gemv: [128][12]
    float* red = sm + 128 * 12;  // gemv: [256][9]
    const unsigned smbase = (unsigned)__cvta_generic_to_shared(sm);

    for (int l = 0; l < LL; l++) {
        const float* Wq = qkvw + (size_t)l * DD * NQKV;
        const float* bq = qkvb + (size_t)l * NQKV;
        const float* Wo = outw + (size_t)l * DD * DD;
        const float* bo = outb + (size_t)l * DD;
        const float* W1 = w1 + (size_t)l * DD * DFF;
        const float* B1 = b1 + (size_t)l * DFF;
        const float* W2 = w2 + (size_t)l * DFF * DD;
        const float* Kc = kc + (size_t)l * BB * HH * TMAX * HD;
        const float* Vc = vc + (size_t)l * BB * HH * TMAX * HD;

        // S0: produce g_h (x for l==0, else LN2 of prev layer). 16 vblocks.
        if (l == 0) {
            for (int i = blockIdx.x * NT + threadIdx.x; i < BB * DD;
                 i += gridDim.x * NT)
                g_h[i] = x[i];
        } else {
            for (int vb = blockIdx.x; vb < 16; vb += gridDim.x)
                ln_stage<16>(g_p2, g_h1, b2 + (size_t)(l - 1) * DD,
                             ln2g + (size_t)(l - 1) * DD,
                             ln2b + (size_t)(l - 1) * DD, g_h, vb, sm);
        }
        gsync();

        // S1: qkv split-K4 (DS=128). 384 vblocks.
        for (int vb = blockIdx.x; vb < 384; vb += gridDim.x) {
            int ks = vb & 3, b0 = ((vb >> 2) & 1) * 8, c0 = (vb >> 3) * 32;
            preload_plain<128>(g_h, DD, ks * 128, b0, xs);
            gemv_core<128>(Wq, NQKV, ks * 128, c0,
                           g_pqkv + (size_t)ks * BB * NQKV, NQKV, b0, xs, red);
        }
        gsync();

        // S2: attention T-split 2, cp.async pipelined. 512 vblocks.
        for (int vb = blockIdx.x; vb < 512; vb += gridDim.x) {
            int c = vb & 1, h = (vb >> 1) & 15, b = vb >> 5;
            attn_chunk(Kc, Vc, bq, kvlen, b, h, c, sm, smbase);
        }
        gsync();

        // S3: outproj split-K16 (DS=32), chunk sum-merge in preload. 512.
        for (int vb = blockIdx.x; vb < 512; vb += gridDim.x) {
            int ks = vb & 15, b0 = ((vb >> 4) & 1) * 8, c0 = (vb >> 5) * 32;
            preload_attn(ks, b0, xs);  // h == ks since DS == HD
            gemv_core<32>(Wo, DD, ks * 32, c0,
                          g_po + (size_t)ks * BB * DD, DD, b0, xs, red);
        }
        gsync();

        // S4: LN1 (merge 16 outproj partials + residual g_h + bo). 16 vblocks.
        for (int vb = blockIdx.x; vb < 16; vb += gridDim.x)
            ln_stage<16>(g_po, g_h, bo, ln1g + (size_t)l * DD,
                         ln1b + (size_t)l * DD, g_h1, vb, sm);
        gsync();

        // S5: mlp1 split-K4 (DS=128). 512 vblocks.
        for (int vb = blockIdx.x; vb < 512; vb += gridDim.x) {
            int ks = vb & 3, b0 = ((vb >> 2) & 1) * 8, c0 = (vb >> 3) * 32;
            preload_plain<128>(g_h1, DD, ks * 128, b0, xs);
            gemv_core<128>(W1, DFF, ks * 128, c0,
                           g_pm1 + (size_t)ks * BB * DFF, DFF, b0, xs, red);
        }
        gsync();

        // S6: mlp2 split-K16 (DS=128), relu+merge in preload. 512 vblocks.
        for (int vb = blockIdx.x; vb < 512; vb += gridDim.x) {
            int ks = vb & 15, b0 = ((vb >> 4) & 1) * 8, c0 = (vb >> 5) * 32;
            preload_relu(B1, ks * 128, b0, xs);
            gemv_core<128>(W2, DD, ks * 128, c0,
                           g_p2 + (size_t)ks * BB * DD, DD, b0, xs, red);
        }
        gsync();
    }

    // final: LN2 of last layer -> d_out. 16 vblocks.
    for (int vb = blockIdx.x; vb < 16; vb += gridDim.x)
        ln_stage<16>(g_p2, g_h1, b2 + (size_t)(LL - 1) * DD,
                     ln2g + (size_t)(LL - 1) * DD,
                     ln2b + (size_t)(LL - 1) * DD, dout, vb, sm);
}

// ---------------- launcher ----------------
extern "C" void kernel_launch(void* const* d_in, const int* in_sizes, int n_in,
                              void* d_out, int out_size) {
    (void)in_sizes; (void)n_in; (void)out_size;
    const float* x    = (const float*)d_in[0];
    const float* kc   = (const float*)d_in[1];
    const float* vc   = (const float*)d_in[2];
    const float* ln1g = (const float*)d_in[3];
    const float* ln1b = (const float*)d_in[4];
    const float* qkvw = (const float*)d_in[5];
    const float* qkvb = (const float*)d_in[6];
    const float* outw = (const float*)d_in[7];
    const float* outb = (const float*)d_in[8];
    const float* ln2g = (const float*)d_in[9];
    const float* ln2b = (const float*)d_in[10];
    const float* w1   = (const float*)d_in[11];
    const float* b1   = (const float*)d_in[12];
    const float* w2   = (const float*)d_in[13];
    const float* b2   = (const float*)d_in[14];
    const int* kvlen  = (const int*)d_in[16];

    static int grid = 0;
    const int SMEM = ATTN_SMEM * 4;  // 38336 bytes (covers gemv's 15360 too)
    if (!grid) {
        cudaFuncSetAttribute(decoder_kernel,
                             cudaFuncAttributeMaxDynamicSharedMemorySize, SMEM);
        int dev = 0;
        cudaGetDevice(&dev);
        cudaDeviceProp prop;
        cudaGetDeviceProperties(&prop, dev);
        int occ = 0;
        cudaOccupancyMaxActiveBlocksPerMultiprocessor(&occ, decoder_kernel,
                                                      NT, SMEM);
        if (occ < 1) occ = 1;
        if (occ > 4) occ = 4;
        grid = prop.multiProcessorCount * occ;
    }

    decoder_kernel<<<grid, NT, SMEM>>>(
        x, kc, vc, ln1g, ln1b, qkvw, qkvb, outw, outb, ln2g, ln2b,
        w1, b1, w2, b2, kvlen, (float*)d_out);
}